// round 4
// baseline (speedup 1.0000x reference)
#include <cuda_runtime.h>

#define LN_EPS   1e-6f
#define INV_TEMP 0.31622776601683794f   // 1/sqrt(10)
#define NT 256

// ---------------- SMEM layout (float offsets; all float4-aligned where needed) ---
#define OFF_WQ    0        // 100
#define OFF_WK    100      // 100
#define OFF_WV    200      // 100
#define OFF_GM    300      // 10
#define OFF_BM    312      // 10
#define OFF_B1    324      // 30
#define OFF_B2    356      // 30
#define OFF_GP    388      // 30
#define OFF_BP    420      // 30
#define OFF_W1T   452      // W1 transposed [i*32+j], 30x30 pad -> 960
#define OFF_W2R   1412     // W2 row-padded [j*32+i]           -> 960
#define OFF_B1P   2372     // 90
#define OFF_B2P   2464     // 90
#define OFF_G1    2556     // 90
#define OFF_BB1   2648     // 90
#define OFF_BC1   2740     // 45 -> 48 (pads zeroed)
#define OFF_WC2   2788     // 135 -> 136
#define OFF_BC2   2924     // 3 -> 4
#define OFF_W1PT  2928     // W1p transposed [i*92+j], 90x90 pad -> 8280
#define OFF_W2PR  11208    // W2p row-padded [j*92+i]            -> 8280
#define OFF_WC1T  19488    // Wc1 transposed [i*48+j], 90x45 pad -> 4320
#define OFF_SX    23808    // per-thread activation: NT * 91
#define SX_STRIDE 91
#define SMEM_FLOATS (OFF_SX + NT * SX_STRIDE)   // 47104 floats = 188416 B

// ---------------------------------------------------------------------------
// helpers (all register arrays indexed only by fully-unrolled constant loops)
// ---------------------------------------------------------------------------

// o[3,10] = in[3,10] @ W^T, W [10,10] torch-Linear layout, W in SMEM.
__device__ __forceinline__ void proj3x10(float o[30], const float in[30],
                                         const float* __restrict__ W)
{
#pragma unroll
    for (int oo = 0; oo < 10; oo++) {
        const float2* wp = reinterpret_cast<const float2*>(W + oo * 10);
        float w[10];
#pragma unroll
        for (int p = 0; p < 5; p++) { float2 u = wp[p]; w[2*p] = u.x; w[2*p+1] = u.y; }
#pragma unroll
        for (int s = 0; s < 3; s++) {
            float a = 0.f;
#pragma unroll
            for (int i = 0; i < 10; i++) a = fmaf(in[s*10+i], w[i], a);
            o[s*10+oo] = a;
        }
    }
}

// One MHA branch: [3,10] q/k/v -> attn -> +residual(q) -> LN(10) -> o[30]
__device__ __forceinline__ void mha_core(float o[30], const float qb[30],
                                         const float kb[30], const float vb[30],
                                         const float* __restrict__ sm)
{
    float qh[30], kh[30];
    proj3x10(qh, qb, sm + OFF_WQ);
    proj3x10(kh, kb, sm + OFF_WK);
    float att[9];
#pragma unroll
    for (int s = 0; s < 3; s++)
#pragma unroll
        for (int tt = 0; tt < 3; tt++) {
            float a = 0.f;
#pragma unroll
            for (int d = 0; d < 10; d++) a = fmaf(qh[s*10+d], kh[tt*10+d], a);
            att[s*3+tt] = a * INV_TEMP;
        }
    float vh[30];
    proj3x10(vh, vb, sm + OFF_WV);
#pragma unroll
    for (int s = 0; s < 3; s++) {
        float t10[10];
        float m = 0.f;
#pragma unroll
        for (int d = 0; d < 10; d++) {
            float a = qb[s*10+d];
            a = fmaf(att[s*3+0], vh[d],      a);
            a = fmaf(att[s*3+1], vh[10+d],   a);
            a = fmaf(att[s*3+2], vh[20+d],   a);
            t10[d] = a; m += a;
        }
        m *= 0.1f;
        float vv = 0.f;
#pragma unroll
        for (int d = 0; d < 10; d++) { float dd = t10[d] - m; vv = fmaf(dd, dd, vv); }
        float r = rsqrtf(fmaf(vv, 0.1f, LN_EPS));
#pragma unroll
        for (int d = 0; d < 10; d++)
            o[s*10+d] = fmaf((t10[d] - m) * r, sm[OFF_GM+d], sm[OFF_BM+d]);
    }
}

// PFF(30) in place on a 30-float SMEM slice (dynamic outer loops -> compact code)
__device__ __forceinline__ void pff30(float* __restrict__ xs,
                                      const float* __restrict__ sm)
{
    float h[32];
#pragma unroll
    for (int j = 0; j < 30; j++) h[j] = sm[OFF_B1+j];
    h[30] = 0.f; h[31] = 0.f;
#pragma unroll 1
    for (int i = 0; i < 30; i++) {
        float xi = xs[i];
        const float4* wr = reinterpret_cast<const float4*>(sm + OFF_W1T + i*32);
#pragma unroll
        for (int j4 = 0; j4 < 8; j4++) {
            float4 w = wr[j4];
            h[4*j4+0] = fmaf(xi, w.x, h[4*j4+0]);
            h[4*j4+1] = fmaf(xi, w.y, h[4*j4+1]);
            h[4*j4+2] = fmaf(xi, w.z, h[4*j4+2]);
            h[4*j4+3] = fmaf(xi, w.w, h[4*j4+3]);
        }
    }
#pragma unroll
    for (int j = 0; j < 30; j++) h[j] = fmaxf(h[j], 0.f);
    h[30] = 0.f; h[31] = 0.f;
    float mean = 0.f;
#pragma unroll 1
    for (int j = 0; j < 30; j++) {
        float a = sm[OFF_B2+j];
        const float4* wr = reinterpret_cast<const float4*>(sm + OFF_W2R + j*32);
#pragma unroll
        for (int i4 = 0; i4 < 8; i4++) {
            float4 w = wr[i4];
            a = fmaf(h[4*i4+0], w.x, a);
            a = fmaf(h[4*i4+1], w.y, a);
            a = fmaf(h[4*i4+2], w.z, a);
            a = fmaf(h[4*i4+3], w.w, a);
        }
        a += xs[j];
        xs[j] = a;
        mean += a;
    }
    mean *= (1.f / 30.f);
    float vv = 0.f;
#pragma unroll 1
    for (int j = 0; j < 30; j++) { float dd = xs[j] - mean; vv = fmaf(dd, dd, vv); }
    float r = rsqrtf(fmaf(vv, 1.f / 30.f, LN_EPS));
#pragma unroll 1
    for (int j = 0; j < 30; j++)
        xs[j] = fmaf((xs[j] - mean) * r, sm[OFF_GP+j], sm[OFF_BP+j]);
}

// ---------------------------------------------------------------------------
// Fused kernel: one thread per row, activation vector in SMEM, weights in SMEM.
// ---------------------------------------------------------------------------
__global__ __launch_bounds__(NT, 1)
void fused_kernel(const float* __restrict__ gq, const float* __restrict__ gk,
                  const float* __restrict__ gv,
                  const float* __restrict__ Wq, const float* __restrict__ Wk,
                  const float* __restrict__ Wv,
                  const float* __restrict__ gm, const float* __restrict__ bm,
                  const float* __restrict__ W1, const float* __restrict__ b1,
                  const float* __restrict__ W2, const float* __restrict__ b2,
                  const float* __restrict__ gp, const float* __restrict__ bp,
                  const float* __restrict__ W1p, const float* __restrict__ b1p,
                  const float* __restrict__ W2p, const float* __restrict__ b2p,
                  const float* __restrict__ g1,  const float* __restrict__ bb1,
                  const float* __restrict__ Wc1, const float* __restrict__ bc1,
                  const float* __restrict__ Wc2, const float* __restrict__ bc2,
                  float* __restrict__ out, int nr)
{
    extern __shared__ float sm[];
    const int t = threadIdx.x;

    // zero weight region (also zeroes all pads)
    for (int i = t; i < OFF_SX; i += NT) sm[i] = 0.f;
    __syncthreads();

    for (int i = t; i < 100; i += NT) { sm[OFF_WQ+i] = Wq[i]; sm[OFF_WK+i] = Wk[i]; sm[OFF_WV+i] = Wv[i]; }
    if (t < 10) { sm[OFF_GM+t] = gm[t]; sm[OFF_BM+t] = bm[t]; }
    if (t >= 32 && t < 62) { int j = t - 32; sm[OFF_B1+j] = b1[j]; sm[OFF_B2+j] = b2[j]; sm[OFF_GP+j] = gp[j]; sm[OFF_BP+j] = bp[j]; }
    for (int idx = t; idx < 900; idx += NT) {
        int j = idx / 30, i = idx % 30;
        sm[OFF_W1T + i*32 + j] = W1[idx];
        sm[OFF_W2R + j*32 + i] = W2[idx];
    }
    if (t >= 64 && t < 154) { int j = t - 64; sm[OFF_B1P+j] = b1p[j]; sm[OFF_B2P+j] = b2p[j]; sm[OFF_G1+j] = g1[j]; sm[OFF_BB1+j] = bb1[j]; }
    for (int idx = t; idx < 8100; idx += NT) {
        int j = idx / 90, i = idx % 90;
        sm[OFF_W1PT + i*92 + j] = W1p[idx];
        sm[OFF_W2PR + j*92 + i] = W2p[idx];
    }
    for (int idx = t; idx < 4050; idx += NT) {
        int j = idx / 90, i = idx % 90;
        sm[OFF_WC1T + i*48 + j] = Wc1[idx];
    }
    if (t >= 160 && t < 205) sm[OFF_BC1 + t - 160] = bc1[t - 160];
    if (t >= 208 && t < 211) sm[OFF_BC2 + t - 208] = bc2[t - 208];
    if (t < 135) sm[OFF_WC2 + t] = Wc2[t];
    __syncthreads();

    const int row = blockIdx.x * NT + t;
    if (row >= nr) return;

    float* __restrict__ myx = sm + OFF_SX + t * SX_STRIDE;  // stride 91: conflict-free

    // ---- phase 1: MHA(q,k,v) + PFF30, per branch ----
    const float2* qr = reinterpret_cast<const float2*>(gq + (size_t)row * 90);
    const float2* kr = reinterpret_cast<const float2*>(gk + (size_t)row * 90);
    const float2* vr = reinterpret_cast<const float2*>(gv + (size_t)row * 90);
#pragma unroll 1
    for (int b = 0; b < 3; b++) {
        float qb[30], kb[30], vb[30];
#pragma unroll
        for (int p = 0; p < 15; p++) {
            float2 a = qr[b*15+p]; qb[2*p] = a.x; qb[2*p+1] = a.y;
            float2 c = kr[b*15+p]; kb[2*p] = c.x; kb[2*p+1] = c.y;
            float2 d = vr[b*15+p]; vb[2*p] = d.x; vb[2*p+1] = d.y;
        }
        float o[30];
        mha_core(o, qb, kb, vb, sm);
#pragma unroll
        for (int d = 0; d < 30; d++) myx[b*30+d] = o[d];
        pff30(myx + b*30, sm);
    }

    // ---- phase 2: MHA(x,x,x) + PFF30, per branch, in place ----
#pragma unroll 1
    for (int b = 0; b < 3; b++) {
        float qb[30];
#pragma unroll
        for (int d = 0; d < 30; d++) qb[d] = myx[b*30+d];
        float o[30];
        mha_core(o, qb, qb, qb, sm);
#pragma unroll
        for (int d = 0; d < 30; d++) myx[b*30+d] = o[d];
        pff30(myx + b*30, sm);
    }

    // ---- PFF(90) ----
    float h[92];
#pragma unroll
    for (int j = 0; j < 90; j++) h[j] = sm[OFF_B1P+j];
    h[90] = 0.f; h[91] = 0.f;
#pragma unroll 1
    for (int i = 0; i < 90; i++) {
        float xi = myx[i];
        const float4* wr = reinterpret_cast<const float4*>(sm + OFF_W1PT + i*92);
#pragma unroll
        for (int j4 = 0; j4 < 23; j4++) {
            float4 w = wr[j4];
            h[4*j4+0] = fmaf(xi, w.x, h[4*j4+0]);
            h[4*j4+1] = fmaf(xi, w.y, h[4*j4+1]);
            h[4*j4+2] = fmaf(xi, w.z, h[4*j4+2]);
            h[4*j4+3] = fmaf(xi, w.w, h[4*j4+3]);
        }
    }
#pragma unroll
    for (int j = 0; j < 90; j++) h[j] = fmaxf(h[j], 0.f);
    h[90] = 0.f; h[91] = 0.f;

    float mean = 0.f;
#pragma unroll 1
    for (int j = 0; j < 90; j++) {
        float a = sm[OFF_B2P+j];
        const float4* wr = reinterpret_cast<const float4*>(sm + OFF_W2PR + j*92);
#pragma unroll
        for (int i4 = 0; i4 < 23; i4++) {
            float4 w = wr[i4];
            a = fmaf(h[4*i4+0], w.x, a);
            a = fmaf(h[4*i4+1], w.y, a);
            a = fmaf(h[4*i4+2], w.z, a);
            a = fmaf(h[4*i4+3], w.w, a);
        }
        a += myx[j];           // residual
        myx[j] = a;
        mean += a;
    }
    mean *= (1.f / 90.f);
    float vv = 0.f;
#pragma unroll 1
    for (int j = 0; j < 90; j++) { float dd = myx[j] - mean; vv = fmaf(dd, dd, vv); }
    float r = rsqrtf(fmaf(vv, 1.f / 90.f, LN_EPS));

    // ---- classifier (LN applied on the fly) + softmax ----
    float c[48];
#pragma unroll
    for (int j = 0; j < 48; j++) c[j] = sm[OFF_BC1+j];   // pads are 0
#pragma unroll 1
    for (int i = 0; i < 90; i++) {
        float xi = fmaf((myx[i] - mean) * r, sm[OFF_G1+i], sm[OFF_BB1+i]);
        const float4* wr = reinterpret_cast<const float4*>(sm + OFF_WC1T + i*48);
#pragma unroll
        for (int j4 = 0; j4 < 12; j4++) {
            float4 w = wr[j4];
            c[4*j4+0] = fmaf(xi, w.x, c[4*j4+0]);
            c[4*j4+1] = fmaf(xi, w.y, c[4*j4+1]);
            c[4*j4+2] = fmaf(xi, w.z, c[4*j4+2]);
            c[4*j4+3] = fmaf(xi, w.w, c[4*j4+3]);
        }
    }
    float lg0 = sm[OFF_BC2+0], lg1 = sm[OFF_BC2+1], lg2 = sm[OFF_BC2+2];
#pragma unroll
    for (int j = 0; j < 45; j++) {
        float a = fmaxf(c[j], 0.f);
        lg0 = fmaf(a, sm[OFF_WC2+j],      lg0);
        lg1 = fmaf(a, sm[OFF_WC2+45+j],   lg1);
        lg2 = fmaf(a, sm[OFF_WC2+90+j],   lg2);
    }
    float mm = fmaxf(lg0, fmaxf(lg1, lg2));
    float e0 = __expf(lg0 - mm), e1 = __expf(lg1 - mm), e2 = __expf(lg2 - mm);
    float inv = __frcp_rn(e0 + e1 + e2);
    out[(size_t)row*3 + 0] = e0 * inv;
    out[(size_t)row*3 + 1] = e1 * inv;
    out[(size_t)row*3 + 2] = e2 * inv;
}

// ---------------------------------------------------------------------------
extern "C" void kernel_launch(void* const* d_in, const int* in_sizes, int n_in,
                              void* d_out, int out_size)
{
    const float* A[24];
    for (int i = 0; i < 24; i++) A[i] = (const float*)d_in[i];

    int nr = in_sizes[0] / 90;
    int blocks = (nr + NT - 1) / NT;
    size_t shmem = (size_t)SMEM_FLOATS * sizeof(float);

    cudaFuncSetAttribute(fused_kernel,
                         cudaFuncAttributeMaxDynamicSharedMemorySize, (int)shmem);

    fused_kernel<<<blocks, NT, shmem>>>(
        A[0],  A[1],  A[2],  A[3],  A[4],  A[5],  A[6],  A[7],
        A[8],  A[9],  A[10], A[11], A[12], A[13], A[14], A[15],
        A[16], A[17], A[18], A[19], A[20], A[21], A[22], A[23],
        (float*)d_out, nr);
}